// round 1
// baseline (speedup 1.0000x reference)
#include <cuda_runtime.h>
#include <math.h>

#define LQ      37440
#define LIN     37440
#define DM      256
#define NHEADS  8
#define CHEAD   32
#define NLEV    4
#define NPTS    4

// level constants (fixed by problem)
__device__ __constant__ int c_lvl_size[4]  = {32, 16, 8, 4};
__device__ __constant__ int c_lvl_start[4] = {0, 32768, 36864, 37376};

// scratch (allocation-free per harness rules)
__device__ float g_value  [LIN * DM];       // [Lin, 8, 32]
__device__ float g_off    [LQ * 384];       // [Lq, h*48 + l*12 + p*3 + c]
__device__ float g_attn   [LQ * 128];       // [Lq, h*16 + l*4 + p] (logits)
__device__ float g_sampled[LQ * DM];        // [Lq, h*32 + c]

// ---------------------------------------------------------------------------
// SGEMM: C[M,N] = A[M,K] @ B[K,N] + bias[N]   (A,B row-major, fp32)
// BM=128, BN=64, BK=16, 256 threads, 8x4 per-thread micro-tile
// ---------------------------------------------------------------------------
#define BM 128
#define BN 64
#define BK 16
#define TM 8
#define TN 4

__global__ __launch_bounds__(256) void sgemm_bias(
    const float* __restrict__ A, const float* __restrict__ B,
    const float* __restrict__ bias, float* __restrict__ C,
    int M, int N, int K)
{
    __shared__ float As[BK][BM];   // transposed store: As[k][m]
    __shared__ float Bs[BK][BN];

    const int tid = threadIdx.x;
    const int bm  = blockIdx.y * BM;
    const int bn  = blockIdx.x * BN;
    const int tx  = tid % (BN / TN);   // 0..15
    const int ty  = tid / (BN / TN);   // 0..15

    float acc[TM][TN];
    #pragma unroll
    for (int i = 0; i < TM; i++)
        #pragma unroll
        for (int j = 0; j < TN; j++) acc[i][j] = 0.f;

    for (int k0 = 0; k0 < K; k0 += BK) {
        // load A tile (BM x BK), store transposed
        #pragma unroll
        for (int i = tid; i < BM * BK; i += 256) {
            int m  = i / BK;
            int kk = i % BK;
            int gm = bm + m;
            As[kk][m] = (gm < M) ? A[(size_t)gm * K + (k0 + kk)] : 0.f;
        }
        // load B tile (BK x BN)
        #pragma unroll
        for (int i = tid; i < BK * BN; i += 256) {
            int kk = i / BN;
            int n  = i % BN;
            int gn = bn + n;
            Bs[kk][n] = (gn < N) ? B[(size_t)(k0 + kk) * N + gn] : 0.f;
        }
        __syncthreads();

        #pragma unroll
        for (int kk = 0; kk < BK; kk++) {
            float ra[TM], rb[TN];
            #pragma unroll
            for (int i = 0; i < TM; i++) ra[i] = As[kk][ty * TM + i];
            #pragma unroll
            for (int j = 0; j < TN; j++) rb[j] = Bs[kk][tx * TN + j];
            #pragma unroll
            for (int i = 0; i < TM; i++)
                #pragma unroll
                for (int j = 0; j < TN; j++)
                    acc[i][j] = fmaf(ra[i], rb[j], acc[i][j]);
        }
        __syncthreads();
    }

    #pragma unroll
    for (int i = 0; i < TM; i++) {
        int gm = bm + ty * TM + i;
        if (gm >= M) continue;
        #pragma unroll
        for (int j = 0; j < TN; j++) {
            int gn = bn + tx * TN + j;
            if (gn < N) C[(size_t)gm * N + gn] = acc[i][j] + bias[gn];
        }
    }
}

// ---------------------------------------------------------------------------
// Sampling: block per query (256 thr = 8 warps), warp = head, lane = channel
// ---------------------------------------------------------------------------
__global__ __launch_bounds__(256) void sample_kernel(
    const float* __restrict__ value,    // [Lin, 256]  (h*32 + c)
    const float* __restrict__ refpts,   // [Lq, 4, 3]
    const float* __restrict__ off,      // [Lq, 384]
    const float* __restrict__ attn,     // [Lq, 128] logits
    float* __restrict__ sampled)        // [Lq, 256]
{
    const int q    = blockIdx.x;
    const int tid  = threadIdx.x;
    const int h    = tid >> 5;
    const int lane = tid & 31;

    __shared__ float s_off[384];
    __shared__ float s_attn[128];
    __shared__ float s_ref[12];

    #pragma unroll
    for (int i = tid; i < 384; i += 256) s_off[i] = off[(size_t)q * 384 + i];
    if (tid < 128) s_attn[tid] = attn[(size_t)q * 128 + tid];
    if (tid < 12)  s_ref[tid]  = refpts[(size_t)q * 12 + tid];
    __syncthreads();

    // per-head softmax over 16 (computed redundantly per lane; smem broadcast)
    float w[16];
    float mx = -1e30f;
    #pragma unroll
    for (int i = 0; i < 16; i++) { w[i] = s_attn[h * 16 + i]; mx = fmaxf(mx, w[i]); }
    float sum = 0.f;
    #pragma unroll
    for (int i = 0; i < 16; i++) { w[i] = __expf(w[i] - mx); sum += w[i]; }
    const float inv = 1.f / sum;

    float acc = 0.f;
    const float* vbase = value + h * CHEAD + lane;

    #pragma unroll
    for (int l = 0; l < NLEV; l++) {
        const int   S     = c_lvl_size[l];
        const int   start = c_lvl_start[l];
        const float fS    = (float)S;
        const float rx = s_ref[l * 3 + 0];
        const float ry = s_ref[l * 3 + 1];
        const float rz = s_ref[l * 3 + 2];

        #pragma unroll
        for (int p = 0; p < NPTS; p++) {
            const int ob = h * 48 + l * 12 + p * 3;
            // H=W=D=S, so loc*dim - 0.5 with off normalized by S:
            const float ix = fmaf(rx, fS, s_off[ob + 0] - 0.5f);
            const float iy = fmaf(ry, fS, s_off[ob + 1] - 0.5f);
            const float iz = fmaf(rz, fS, s_off[ob + 2] - 0.5f);

            const float x0f = floorf(ix), y0f = floorf(iy), z0f = floorf(iz);
            const float fx = ix - x0f, fy = iy - y0f, fz = iz - z0f;
            const int x0 = (int)x0f, y0 = (int)y0f, z0 = (int)z0f;

            const float wp = w[l * 4 + p] * inv;

            #pragma unroll
            for (int dz = 0; dz < 2; dz++) {
                const int zc = z0 + dz;
                if ((unsigned)zc >= (unsigned)S) continue;
                const float wz = dz ? fz : 1.f - fz;
                #pragma unroll
                for (int dy = 0; dy < 2; dy++) {
                    const int yc = y0 + dy;
                    if ((unsigned)yc >= (unsigned)S) continue;
                    const float wy = dy ? fy : 1.f - fy;
                    #pragma unroll
                    for (int dx = 0; dx < 2; dx++) {
                        const int xc = x0 + dx;
                        if ((unsigned)xc >= (unsigned)S) continue;
                        const float wx = dx ? fx : 1.f - fx;
                        const int idx = start + (zc * S + yc) * S + xc;
                        acc = fmaf(wp * wz * wy * wx,
                                   __ldg(vbase + (size_t)idx * DM), acc);
                    }
                }
            }
        }
    }

    sampled[(size_t)q * DM + h * CHEAD + lane] = acc;
}

// ---------------------------------------------------------------------------
extern "C" void kernel_launch(void* const* d_in, const int* in_sizes, int n_in,
                              void* d_out, int out_size)
{
    const float* query   = (const float*)d_in[0];
    const float* refpts  = (const float*)d_in[1];
    const float* inflat  = (const float*)d_in[2];
    // d_in[3] spatial shapes, d_in[4] level starts: fixed constants, unused
    const float* W_value = (const float*)d_in[5];
    const float* b_value = (const float*)d_in[6];
    const float* W_off   = (const float*)d_in[7];
    const float* b_off   = (const float*)d_in[8];
    const float* W_attn  = (const float*)d_in[9];
    const float* b_attn  = (const float*)d_in[10];
    const float* W_out   = (const float*)d_in[11];
    const float* b_out   = (const float*)d_in[12];
    float* out = (float*)d_out;

    float *p_value, *p_off, *p_attn, *p_sampled;
    cudaGetSymbolAddress((void**)&p_value,   g_value);
    cudaGetSymbolAddress((void**)&p_off,     g_off);
    cudaGetSymbolAddress((void**)&p_attn,    g_attn);
    cudaGetSymbolAddress((void**)&p_sampled, g_sampled);

    dim3 block(256);

    // 1) value = input_flatten @ W_value + b_value     [Lin, 256]
    {
        dim3 grid(DM / BN, (LIN + BM - 1) / BM);
        sgemm_bias<<<grid, block>>>(inflat, W_value, b_value, p_value, LIN, DM, DM);
    }
    // 2) off = query @ W_off + b_off                   [Lq, 384]
    {
        dim3 grid(384 / BN, (LQ + BM - 1) / BM);
        sgemm_bias<<<grid, block>>>(query, W_off, b_off, p_off, LQ, 384, DM);
    }
    // 3) attn logits = query @ W_attn + b_attn         [Lq, 128]
    {
        dim3 grid(128 / BN, (LQ + BM - 1) / BM);
        sgemm_bias<<<grid, block>>>(query, W_attn, b_attn, p_attn, LQ, 128, DM);
    }
    // 4) softmax + trilinear deformable sampling       [Lq, 256]
    {
        sample_kernel<<<LQ, block>>>(p_value, refpts, p_off, p_attn, p_sampled);
    }
    // 5) out = sampled @ W_out + b_out                 [Lq, 256]
    {
        dim3 grid(DM / BN, (LQ + BM - 1) / BM);
        sgemm_bias<<<grid, block>>>(p_sampled, W_out, b_out, out, LQ, DM, DM);
    }
}

// round 2
// speedup vs baseline: 1.8259x; 1.8259x over previous
#include <cuda_runtime.h>
#include <math.h>

#define LQ      37440
#define LIN     37440
#define DM      256
#define NHEADS  8
#define CHEAD   32
#define NLEV    4
#define NPTS    4

// scratch (allocation-free per harness rules)
__device__ float g_value  [LIN * DM];       // [Lin, 8, 32]
__device__ float g_off    [LQ * 384];       // [Lq, h*48 + l*12 + p*3 + c]
__device__ float g_attn   [LQ * 128];       // [Lq, h*16 + l*4 + p] (logits)
__device__ float g_sampled[LQ * DM];        // [Lq, h*32 + c]

// ---------------------------------------------------------------------------
// SGEMM: C[M,N] = A[M,K] @ B[K,N] + bias[N]   (row-major fp32)
// BM=128, BN=128, BK=16, 256 threads, 8x8 micro-tile, float4 everywhere.
// N must be a multiple of 128, K a multiple of 16 (true here: N in
// {128,256,384}, K=256). Only M is bounds-checked.
// ---------------------------------------------------------------------------
#define BM 128
#define BN 128
#define BK 16

__global__ __launch_bounds__(256) void sgemm_bias(
    const float* __restrict__ A, const float* __restrict__ B,
    const float* __restrict__ bias, float* __restrict__ C,
    int M, int N, int K)
{
    __shared__ float As[BK][BM];   // transposed: As[k][m]
    __shared__ float Bs[BK][BN];

    const int tid = threadIdx.x;
    const int bm  = blockIdx.y * BM;
    const int bn  = blockIdx.x * BN;
    const int tx  = tid & 15;     // 0..15  (n direction)
    const int ty  = tid >> 4;     // 0..15  (m direction)

    float acc[8][8];
    #pragma unroll
    for (int i = 0; i < 8; i++)
        #pragma unroll
        for (int j = 0; j < 8; j++) acc[i][j] = 0.f;

    for (int k0 = 0; k0 < K; k0 += BK) {
        // A tile: 128x16 = 512 float4 loads, store transposed
        #pragma unroll
        for (int it = 0; it < 2; it++) {
            int f  = tid + it * 256;          // float4 id 0..511
            int m  = f >> 2;
            int k4 = f & 3;
            int gm = bm + m;
            float4 a = make_float4(0.f, 0.f, 0.f, 0.f);
            if (gm < M)
                a = *(const float4*)(A + (size_t)gm * K + k0 + k4 * 4);
            As[k4 * 4 + 0][m] = a.x;
            As[k4 * 4 + 1][m] = a.y;
            As[k4 * 4 + 2][m] = a.z;
            As[k4 * 4 + 3][m] = a.w;
        }
        // B tile: 16x128 = 512 float4 loads
        #pragma unroll
        for (int it = 0; it < 2; it++) {
            int f  = tid + it * 256;
            int kk = f >> 5;
            int n4 = f & 31;
            *(float4*)&Bs[kk][n4 * 4] =
                *(const float4*)(B + (size_t)(k0 + kk) * N + bn + n4 * 4);
        }
        __syncthreads();

        #pragma unroll
        for (int kk = 0; kk < BK; kk++) {
            float ra[8], rb[8];
            *(float4*)&ra[0] = *(const float4*)&As[kk][ty * 8];
            *(float4*)&ra[4] = *(const float4*)&As[kk][ty * 8 + 4];
            *(float4*)&rb[0] = *(const float4*)&Bs[kk][tx * 8];
            *(float4*)&rb[4] = *(const float4*)&Bs[kk][tx * 8 + 4];
            #pragma unroll
            for (int i = 0; i < 8; i++)
                #pragma unroll
                for (int j = 0; j < 8; j++)
                    acc[i][j] = fmaf(ra[i], rb[j], acc[i][j]);
        }
        __syncthreads();
    }

    float bv[8];
    *(float4*)&bv[0] = *(const float4*)(bias + bn + tx * 8);
    *(float4*)&bv[4] = *(const float4*)(bias + bn + tx * 8 + 4);

    #pragma unroll
    for (int i = 0; i < 8; i++) {
        int gm = bm + ty * 8 + i;
        if (gm >= M) continue;
        float4 o0 = make_float4(acc[i][0] + bv[0], acc[i][1] + bv[1],
                                acc[i][2] + bv[2], acc[i][3] + bv[3]);
        float4 o1 = make_float4(acc[i][4] + bv[4], acc[i][5] + bv[5],
                                acc[i][6] + bv[6], acc[i][7] + bv[7]);
        *(float4*)(C + (size_t)gm * N + bn + tx * 8)     = o0;
        *(float4*)(C + (size_t)gm * N + bn + tx * 8 + 4) = o1;
    }
}

// ---------------------------------------------------------------------------
// Sampling, two-phase:
//  phase 1: 128 threads = (head, point) pairs -> softmax + 8 corners each
//           packed (weight, idx*256) float2 into smem
//  phase 2: warp = head, lane = channel; stream 128 corners, predicated LDG
// ---------------------------------------------------------------------------
__global__ __launch_bounds__(256) void sample_kernel(
    const float* __restrict__ value,    // [Lin, 256]
    const float* __restrict__ refpts,   // [Lq, 4, 3]
    const float* __restrict__ off,      // [Lq, 384]
    const float* __restrict__ attn,     // [Lq, 128] logits
    float* __restrict__ sampled)        // [Lq, 256]
{
    const int q   = blockIdx.x;
    const int tid = threadIdx.x;

    __shared__ float2 s_cwi[128 * 8];   // (weight, idx*256 bitcast), 8KB

    if (tid < 128) {
        const int h  = tid >> 4;        // head
        const int p  = tid & 15;        // level*4 + point
        const int l  = p >> 2;
        const int pt = p & 3;

        // softmax over the 16-lane group (one head per half-warp)
        float logit = attn[(size_t)q * 128 + tid];
        float mx = logit;
        #pragma unroll
        for (int m = 8; m; m >>= 1)
            mx = fmaxf(mx, __shfl_xor_sync(0xffffffffu, mx, m));
        float e = __expf(logit - mx);
        float sum = e;
        #pragma unroll
        for (int m = 8; m; m >>= 1)
            sum += __shfl_xor_sync(0xffffffffu, sum, m);
        const float wp = e / sum;

        const int   S     = 32 >> l;
        const int   start = (l == 0) ? 0 : (l == 1) ? 32768
                          : (l == 2) ? 36864 : 37376;
        const float fS    = (float)S;

        const float rx = refpts[(size_t)q * 12 + l * 3 + 0];
        const float ry = refpts[(size_t)q * 12 + l * 3 + 1];
        const float rz = refpts[(size_t)q * 12 + l * 3 + 2];

        const size_t ob = (size_t)q * 384 + h * 48 + l * 12 + pt * 3;
        const float ix = fmaf(rx, fS, off[ob + 0] - 0.5f);
        const float iy = fmaf(ry, fS, off[ob + 1] - 0.5f);
        const float iz = fmaf(rz, fS, off[ob + 2] - 0.5f);

        const float x0f = floorf(ix), y0f = floorf(iy), z0f = floorf(iz);
        const float fx = ix - x0f, fy = iy - y0f, fz = iz - z0f;
        const int x0 = (int)x0f, y0 = (int)y0f, z0 = (int)z0f;

        const float wxv[2] = {1.f - fx, fx};
        const float wyv[2] = {1.f - fy, fy};
        const float wzv[2] = {1.f - fz, fz};

        #pragma unroll
        for (int dz = 0; dz < 2; dz++) {
            const int zc = z0 + dz;
            #pragma unroll
            for (int dy = 0; dy < 2; dy++) {
                const int yc = y0 + dy;
                #pragma unroll
                for (int dx = 0; dx < 2; dx++) {
                    const int xc = x0 + dx;
                    const int c  = dz * 4 + dy * 2 + dx;
                    const bool valid = ((unsigned)xc < (unsigned)S) &
                                       ((unsigned)yc < (unsigned)S) &
                                       ((unsigned)zc < (unsigned)S);
                    float w  = valid ? wp * wzv[dz] * wyv[dy] * wxv[dx] : 0.f;
                    int  idx = valid ? (start + (zc * S + yc) * S + xc) * DM : 0;
                    s_cwi[tid * 8 + c] = make_float2(w, __int_as_float(idx));
                }
            }
        }
    }
    __syncthreads();

    const int h    = tid >> 5;
    const int lane = tid & 31;
    const float* vbase = value + h * CHEAD + lane;
    const float4* cwi4 = (const float4*)(s_cwi + h * 128);  // 64 float4s

    float a0 = 0.f, a1 = 0.f, a2 = 0.f, a3 = 0.f;
    #pragma unroll 4
    for (int j = 0; j < 64; j += 2) {
        float4 v0 = cwi4[j];
        float4 v1 = cwi4[j + 1];
        if (v0.x != 0.f) a0 = fmaf(v0.x, __ldg(vbase + __float_as_int(v0.y)), a0);
        if (v0.z != 0.f) a1 = fmaf(v0.z, __ldg(vbase + __float_as_int(v0.w)), a1);
        if (v1.x != 0.f) a2 = fmaf(v1.x, __ldg(vbase + __float_as_int(v1.y)), a2);
        if (v1.z != 0.f) a3 = fmaf(v1.z, __ldg(vbase + __float_as_int(v1.w)), a3);
    }

    sampled[(size_t)q * DM + tid] = (a0 + a1) + (a2 + a3);
}

// ---------------------------------------------------------------------------
extern "C" void kernel_launch(void* const* d_in, const int* in_sizes, int n_in,
                              void* d_out, int out_size)
{
    const float* query   = (const float*)d_in[0];
    const float* refpts  = (const float*)d_in[1];
    const float* inflat  = (const float*)d_in[2];
    const float* W_value = (const float*)d_in[5];
    const float* b_value = (const float*)d_in[6];
    const float* W_off   = (const float*)d_in[7];
    const float* b_off   = (const float*)d_in[8];
    const float* W_attn  = (const float*)d_in[9];
    const float* b_attn  = (const float*)d_in[10];
    const float* W_out   = (const float*)d_in[11];
    const float* b_out   = (const float*)d_in[12];
    float* out = (float*)d_out;

    float *p_value, *p_off, *p_attn, *p_sampled;
    cudaGetSymbolAddress((void**)&p_value,   g_value);
    cudaGetSymbolAddress((void**)&p_off,     g_off);
    cudaGetSymbolAddress((void**)&p_attn,    g_attn);
    cudaGetSymbolAddress((void**)&p_sampled, g_sampled);

    dim3 block(256);
    const int mb = (LQ + BM - 1) / BM;

    // 1) value = input_flatten @ W_value + b_value     [Lin, 256]
    sgemm_bias<<<dim3(DM / BN, mb), block>>>(inflat, W_value, b_value, p_value, LIN, DM, DM);
    // 2) off = query @ W_off + b_off                   [Lq, 384]
    sgemm_bias<<<dim3(384 / BN, mb), block>>>(query, W_off, b_off, p_off, LQ, 384, DM);
    // 3) attn logits = query @ W_attn + b_attn         [Lq, 128]
    sgemm_bias<<<dim3(128 / BN, mb), block>>>(query, W_attn, b_attn, p_attn, LQ, 128, DM);
    // 4) softmax + trilinear deformable sampling       [Lq, 256]
    sample_kernel<<<LQ, block>>>(p_value, refpts, p_off, p_attn, p_sampled);
    // 5) out = sampled @ W_out + b_out                 [Lq, 256]
    sgemm_bias<<<dim3(DM / BN, mb), block>>>(p_sampled, W_out, b_out, out, LQ, DM, DM);
}

// round 3
// speedup vs baseline: 2.8566x; 1.5644x over previous
#include <cuda_runtime.h>
#include <math.h>
#include <stdint.h>

#define LQ      37440
#define LIN     37440
#define DM      256
#define NHEADS  8
#define CHEAD   32
#define NLEV    4
#define NPTS    4

// scratch (allocation-free per harness rules)
__device__ float g_value  [LIN * DM];
__device__ float g_off    [LQ * 384];
__device__ float g_attn   [LQ * 128];
__device__ float g_sampled[LQ * DM];

// ---------------------------------------------------------------------------
// tf32 tensor-core GEMM: C[M,N] = A[M,K] @ B[K,N] + bias[N]
// BM=128, BN=128, BK=32, 256 threads (8 warps, 2x4), warp tile 64x32,
// mma.sync.m16n8k8.tf32. N % 128 == 0, K % 32 == 0. M bounds-checked.
// ---------------------------------------------------------------------------
#define GBM 128
#define GBN 128
#define GBK 32
#define APITCH 36     // 32 + 4 -> A frag LDS bank == lane (conflict-free)
#define BPITCH 136    // 128 + 8 -> B frag bank = 8*tg + g (conflict-free)

__device__ __forceinline__ uint32_t f2tf32(float x) {
    uint32_t u;
    asm("cvt.rna.tf32.f32 %0, %1;" : "=r"(u) : "f"(x));
    return u;
}

#define MMA_TF32(d, a, b)                                                     \
    asm volatile(                                                             \
        "mma.sync.aligned.m16n8k8.row.col.f32.tf32.tf32.f32 "                 \
        "{%0,%1,%2,%3}, {%4,%5,%6,%7}, {%8,%9}, {%0,%1,%2,%3};"               \
        : "+f"((d)[0]), "+f"((d)[1]), "+f"((d)[2]), "+f"((d)[3])              \
        : "r"((a)[0]), "r"((a)[1]), "r"((a)[2]), "r"((a)[3]),                 \
          "r"((b)[0]), "r"((b)[1]))

__global__ __launch_bounds__(256, 2) void gemm_tf32_bias(
    const float* __restrict__ A, const float* __restrict__ B,
    const float* __restrict__ bias, float* __restrict__ C,
    int M, int N, int K)
{
    __shared__ uint32_t As[GBM * APITCH];
    __shared__ uint32_t Bs[GBK * BPITCH];

    const int tid    = threadIdx.x;
    const int wid    = tid >> 5;
    const int lane   = tid & 31;
    const int g      = lane >> 2;   // groupID 0..7
    const int tg     = lane & 3;    // threadInGroup 0..3
    const int warp_m = (wid >> 2) * 64;  // 0 or 64
    const int warp_n = (wid & 3) * 32;   // 0,32,64,96

    const int bm = blockIdx.y * GBM;
    const int bn = blockIdx.x * GBN;

    float acc[4][4][4];
    #pragma unroll
    for (int i = 0; i < 4; i++)
        #pragma unroll
        for (int j = 0; j < 4; j++)
            #pragma unroll
            for (int r = 0; r < 4; r++) acc[i][j][r] = 0.f;

    for (int k0 = 0; k0 < K; k0 += GBK) {
        // --- A tile: 128 x 32 (1024 float4, 4 per thread), cvt to tf32 ---
        #pragma unroll
        for (int it = 0; it < 4; it++) {
            int f  = tid + it * 256;
            int m  = f >> 3;
            int k4 = (f & 7) * 4;
            int gm = bm + m;
            float4 a = make_float4(0.f, 0.f, 0.f, 0.f);
            if (gm < M)
                a = *(const float4*)(A + (size_t)gm * K + k0 + k4);
            uint32_t* dst = &As[m * APITCH + k4];
            dst[0] = f2tf32(a.x); dst[1] = f2tf32(a.y);
            dst[2] = f2tf32(a.z); dst[3] = f2tf32(a.w);
        }
        // --- B tile: 32 x 128 ---
        #pragma unroll
        for (int it = 0; it < 4; it++) {
            int f  = tid + it * 256;
            int kk = f >> 5;
            int n4 = (f & 31) * 4;
            float4 b = *(const float4*)(B + (size_t)(k0 + kk) * N + bn + n4);
            uint32_t* dst = &Bs[kk * BPITCH + n4];
            dst[0] = f2tf32(b.x); dst[1] = f2tf32(b.y);
            dst[2] = f2tf32(b.z); dst[3] = f2tf32(b.w);
        }
        __syncthreads();

        #pragma unroll
        for (int ks = 0; ks < 4; ks++) {
            const int k8 = ks * 8;
            uint32_t afr[4][4], bfr[4][2];
            #pragma unroll
            for (int mi = 0; mi < 4; mi++) {
                int rb = warp_m + mi * 16 + g;
                afr[mi][0] = As[(rb)     * APITCH + k8 + tg];
                afr[mi][1] = As[(rb + 8) * APITCH + k8 + tg];
                afr[mi][2] = As[(rb)     * APITCH + k8 + tg + 4];
                afr[mi][3] = As[(rb + 8) * APITCH + k8 + tg + 4];
            }
            #pragma unroll
            for (int ni = 0; ni < 4; ni++) {
                int col = warp_n + ni * 8 + g;
                bfr[ni][0] = Bs[(k8 + tg)     * BPITCH + col];
                bfr[ni][1] = Bs[(k8 + tg + 4) * BPITCH + col];
            }
            #pragma unroll
            for (int mi = 0; mi < 4; mi++)
                #pragma unroll
                for (int ni = 0; ni < 4; ni++)
                    MMA_TF32(acc[mi][ni], afr[mi], bfr[ni]);
        }
        __syncthreads();
    }

    // --- epilogue: bias + store (c0,c1 contiguous -> float2) ---
    #pragma unroll
    for (int ni = 0; ni < 4; ni++) {
        const int col = bn + warp_n + ni * 8 + tg * 2;
        const float b0 = bias[col], b1 = bias[col + 1];
        #pragma unroll
        for (int mi = 0; mi < 4; mi++) {
            int r0 = bm + warp_m + mi * 16 + g;
            if (r0 < M)
                *(float2*)(C + (size_t)r0 * N + col) =
                    make_float2(acc[mi][ni][0] + b0, acc[mi][ni][1] + b1);
            int r1 = r0 + 8;
            if (r1 < M)
                *(float2*)(C + (size_t)r1 * N + col) =
                    make_float2(acc[mi][ni][2] + b0, acc[mi][ni][3] + b1);
        }
    }
}

// ---------------------------------------------------------------------------
// Sampling: 2 queries per block.
//  phase 1: 256 thr = 2 x 128 (head,point) pairs -> softmax + 8 corners
//  phase 2: warp = head; accumulate both queries
// ---------------------------------------------------------------------------
__global__ __launch_bounds__(256) void sample_kernel(
    const float* __restrict__ value,    // [Lin, 256]
    const float* __restrict__ refpts,   // [Lq, 4, 3]
    const float* __restrict__ off,      // [Lq, 384]
    const float* __restrict__ attn,     // [Lq, 128] logits
    float* __restrict__ sampled)        // [Lq, 256]
{
    const int q0  = blockIdx.x * 2;
    const int tid = threadIdx.x;

    __shared__ float2 s_cwi[2][128 * 8];   // (weight, idx*256 bitcast), 16KB

    {
        const int qi = tid >> 7;        // 0 or 1
        const int t  = tid & 127;
        const int q  = q0 + qi;
        const int h  = t >> 4;
        const int p  = t & 15;
        const int l  = p >> 2;
        const int pt = p & 3;

        // softmax over the 16-lane group
        float logit = attn[(size_t)q * 128 + t];
        float mx = logit;
        #pragma unroll
        for (int m = 8; m; m >>= 1)
            mx = fmaxf(mx, __shfl_xor_sync(0xffffffffu, mx, m));
        float e = __expf(logit - mx);
        float sum = e;
        #pragma unroll
        for (int m = 8; m; m >>= 1)
            sum += __shfl_xor_sync(0xffffffffu, sum, m);
        const float wp = e / sum;

        const int   S     = 32 >> l;
        const int   start = (l == 0) ? 0 : (l == 1) ? 32768
                          : (l == 2) ? 36864 : 37376;
        const float fS    = (float)S;

        const float rx = refpts[(size_t)q * 12 + l * 3 + 0];
        const float ry = refpts[(size_t)q * 12 + l * 3 + 1];
        const float rz = refpts[(size_t)q * 12 + l * 3 + 2];

        const size_t ob = (size_t)q * 384 + h * 48 + l * 12 + pt * 3;
        const float ix = fmaf(rx, fS, off[ob + 0] - 0.5f);
        const float iy = fmaf(ry, fS, off[ob + 1] - 0.5f);
        const float iz = fmaf(rz, fS, off[ob + 2] - 0.5f);

        const float x0f = floorf(ix), y0f = floorf(iy), z0f = floorf(iz);
        const float fx = ix - x0f, fy = iy - y0f, fz = iz - z0f;
        const int x0 = (int)x0f, y0 = (int)y0f, z0 = (int)z0f;

        const float wxv[2] = {1.f - fx, fx};
        const float wyv[2] = {1.f - fy, fy};
        const float wzv[2] = {1.f - fz, fz};

        #pragma unroll
        for (int dz = 0; dz < 2; dz++) {
            const int zc = z0 + dz;
            #pragma unroll
            for (int dy = 0; dy < 2; dy++) {
                const int yc = y0 + dy;
                #pragma unroll
                for (int dx = 0; dx < 2; dx++) {
                    const int xc = x0 + dx;
                    const int c  = dz * 4 + dy * 2 + dx;
                    const bool valid = ((unsigned)xc < (unsigned)S) &
                                       ((unsigned)yc < (unsigned)S) &
                                       ((unsigned)zc < (unsigned)S);
                    float w  = valid ? wp * wzv[dz] * wyv[dy] * wxv[dx] : 0.f;
                    int  idx = valid ? (start + (zc * S + yc) * S + xc) * DM : 0;
                    s_cwi[qi][t * 8 + c] = make_float2(w, __int_as_float(idx));
                }
            }
        }
    }
    __syncthreads();

    const int h    = tid >> 5;
    const int lane = tid & 31;
    const float* vbase = value + h * CHEAD + lane;

    #pragma unroll
    for (int qi = 0; qi < 2; qi++) {
        const float4* cwi4 = (const float4*)(s_cwi[qi] + h * 128);  // 64 float4
        float a0 = 0.f, a1 = 0.f, a2 = 0.f, a3 = 0.f;
        #pragma unroll 4
        for (int j = 0; j < 64; j += 2) {
            float4 v0 = cwi4[j];
            float4 v1 = cwi4[j + 1];
            if (v0.x != 0.f) a0 = fmaf(v0.x, __ldg(vbase + __float_as_int(v0.y)), a0);
            if (v0.z != 0.f) a1 = fmaf(v0.z, __ldg(vbase + __float_as_int(v0.w)), a1);
            if (v1.x != 0.f) a2 = fmaf(v1.x, __ldg(vbase + __float_as_int(v1.y)), a2);
            if (v1.z != 0.f) a3 = fmaf(v1.z, __ldg(vbase + __float_as_int(v1.w)), a3);
        }
        sampled[(size_t)(q0 + qi) * DM + h * CHEAD + lane] = (a0 + a1) + (a2 + a3);
    }
}

// ---------------------------------------------------------------------------
extern "C" void kernel_launch(void* const* d_in, const int* in_sizes, int n_in,
                              void* d_out, int out_size)
{
    const float* query   = (const float*)d_in[0];
    const float* refpts  = (const float*)d_in[1];
    const float* inflat  = (const float*)d_in[2];
    const float* W_value = (const float*)d_in[5];
    const float* b_value = (const float*)d_in[6];
    const float* W_off   = (const float*)d_in[7];
    const float* b_off   = (const float*)d_in[8];
    const float* W_attn  = (const float*)d_in[9];
    const float* b_attn  = (const float*)d_in[10];
    const float* W_out   = (const float*)d_in[11];
    const float* b_out   = (const float*)d_in[12];
    float* out = (float*)d_out;

    float *p_value, *p_off, *p_attn, *p_sampled;
    cudaGetSymbolAddress((void**)&p_value,   g_value);
    cudaGetSymbolAddress((void**)&p_off,     g_off);
    cudaGetSymbolAddress((void**)&p_attn,    g_attn);
    cudaGetSymbolAddress((void**)&p_sampled, g_sampled);

    dim3 block(256);
    const int mb = (LQ + GBM - 1) / GBM;   // 293

    gemm_tf32_bias<<<dim3(DM / GBN, mb), block>>>(inflat, W_value, b_value, p_value, LIN, DM, DM);
    gemm_tf32_bias<<<dim3(384 / GBN, mb), block>>>(query, W_off, b_off, p_off, LQ, 384, DM);
    gemm_tf32_bias<<<dim3(128 / GBN, mb), block>>>(query, W_attn, b_attn, p_attn, LQ, 128, DM);
    sample_kernel<<<LQ / 2, block>>>(p_value, refpts, p_off, p_attn, p_sampled);
    gemm_tf32_bias<<<dim3(DM / GBN, mb), block>>>(p_sampled, W_out, b_out, out, LQ, DM, DM);
}